// round 11
// baseline (speedup 1.0000x reference)
#include <cuda_runtime.h>

#define Bsz   128
#define TM1   255
#define NIN   256
#define Hd    256
#define BT    (Bsz * TM1)      /* 32640 */
#define G4H   1024

// ---------------- device scratch (static allocation only) ----------------
__device__ float g_G[(size_t)BT * G4H];   // 133.7 MB: x_tilde@W + b

// ---------------- cluster helpers ----------------------------------------
__device__ __forceinline__ unsigned smem_u32(const void* p) {
    unsigned r;
    asm("{ .reg .u64 t; cvta.to.shared.u64 t, %1; cvt.u32.u64 %0, t; }"
        : "=r"(r) : "l"(p));
    return r;
}
__device__ __forceinline__ unsigned mapa_u32(unsigned a, unsigned rk) {
    unsigned o; asm("mapa.shared::cluster.u32 %0, %1, %2;" : "=r"(o) : "r"(a), "r"(rk));
    return o;
}
__device__ __forceinline__ void st_remote_f32(unsigned a, float v) {
    asm volatile("st.shared::cluster.f32 [%0], %1;" :: "r"(a), "f"(v) : "memory");
}
#define CLUSTER_SYNC() do { \
    asm volatile("barrier.cluster.arrive.aligned;" ::: "memory"); \
    asm volatile("barrier.cluster.wait.aligned;"   ::: "memory"); } while (0)

__device__ __forceinline__ float sigm_f(float x) {
    return 1.0f / (1.0f + __expf(-x));
}
__device__ __forceinline__ float tanh_f(float x) {
    return 2.0f / (1.0f + __expf(-2.0f * x)) - 1.0f;
}

// ---------------- kernel 1: alpha (softmax over inputs) + X_tilde --------
// alpha[b,n] = softmax_n( sum_t X[b,t,n] * W_attn[2H + t] )  (h/c/b_attn terms
// are constant over n and cancel in the softmax). 512 threads: (n, t-half).
__global__ __launch_bounds__(512) void alpha_kernel(const float* __restrict__ X,
                                                    const float* __restrict__ W_attn,
                                                    float* __restrict__ out_xt) {
    __shared__ float wx[TM1];
    __shared__ float part[512];
    __shared__ float red[256];
    __shared__ float alph[256];
    const int tid = threadIdx.x;
    const int b   = blockIdx.x;
    const int n   = tid & 255;
    const int th  = tid >> 8;            // t-half: 0 -> [0,128), 1 -> [128,255)
    if (tid < TM1) wx[tid] = W_attn[2 * Hd + tid];
    __syncthreads();

    const float* Xb = X + (size_t)b * TM1 * NIN;
    const int t_lo = th * 128;
    const int t_hi = th ? TM1 : 128;
    float e0 = 0.f, e1 = 0.f, e2 = 0.f, e3 = 0.f;
    int t = t_lo;
#pragma unroll 1
    for (; t + 4 <= t_hi; t += 4) {
        e0 = fmaf(Xb[(t + 0) * NIN + n], wx[t + 0], e0);
        e1 = fmaf(Xb[(t + 1) * NIN + n], wx[t + 1], e1);
        e2 = fmaf(Xb[(t + 2) * NIN + n], wx[t + 2], e2);
        e3 = fmaf(Xb[(t + 3) * NIN + n], wx[t + 3], e3);
    }
    for (; t < t_hi; t++) e0 = fmaf(Xb[t * NIN + n], wx[t], e0);
    part[tid] = (e0 + e1) + (e2 + e3);
    __syncthreads();

    if (tid < 256) {
        float e = part[n] + part[n + 256];
        part[n] = e;          // reuse as per-n e value
        red[n]  = e;
    }
    __syncthreads();
    for (int s = 128; s > 0; s >>= 1) {
        if (tid < s) red[tid] = fmaxf(red[tid], red[tid + s]);
        __syncthreads();
    }
    const float m = red[0];
    __syncthreads();
    if (tid < 256) red[n] = __expf(part[n] - m);
    __syncthreads();
    if (tid < 256) part[n] = red[n];     // keep p
    for (int s = 128; s > 0; s >>= 1) {
        if (tid < s) red[tid] += red[tid + s];
        __syncthreads();
    }
    if (tid < 256) alph[n] = part[n] / red[0];
    __syncthreads();

    const float a = alph[n];
    float* outb = out_xt + (size_t)b * TM1 * NIN;
#pragma unroll 4
    for (int tt = t_lo; tt < t_hi; tt++) outb[tt * NIN + n] = a * Xb[tt * NIN + n];
}

// ---------------- kernel 2: G = X_tilde @ W_lstm + b_lstm ----------------
// Plain-FFMA version (byte-identical logic to the best-measured R4 kernel).
__global__ __launch_bounds__(256, 2) void gemm_kernel(const float* __restrict__ A,
                                                      const float* __restrict__ W,
                                                      const float* __restrict__ bias) {
    __shared__ float As[8][128];
    __shared__ float Bs[8][128];
    const int tid  = threadIdx.x;
    const int row0 = blockIdx.y * 128;
    const int col0 = blockIdx.x * 128;

    float acc[8][8];
#pragma unroll
    for (int i = 0; i < 8; i++)
#pragma unroll
        for (int j = 0; j < 8; j++) acc[i][j] = 0.f;

    const int tr = (tid >> 4) << 3;
    const int tc = (tid & 15) << 3;
    const int am = tid >> 1,  ak = (tid & 1) << 2;
    const int bk = tid >> 5,  bc = (tid & 31) << 2;

    for (int k0 = 0; k0 < 256; k0 += 8) {
        float4 av = *(const float4*)(A + (size_t)(row0 + am) * 256 + k0 + ak);
        As[ak + 0][am] = av.x; As[ak + 1][am] = av.y;
        As[ak + 2][am] = av.z; As[ak + 3][am] = av.w;
        float4 bv = *(const float4*)(W + (size_t)(k0 + bk) * 1024 + col0 + bc);
        *(float4*)&Bs[bk][bc] = bv;
        __syncthreads();
#pragma unroll
        for (int k = 0; k < 8; k++) {
            float a[8], bb[8];
            *(float4*)&a[0]  = *(const float4*)&As[k][tr];
            *(float4*)&a[4]  = *(const float4*)&As[k][tr + 4];
            *(float4*)&bb[0] = *(const float4*)&Bs[k][tc];
            *(float4*)&bb[4] = *(const float4*)&Bs[k][tc + 4];
#pragma unroll
            for (int i = 0; i < 8; i++)
#pragma unroll
                for (int j = 0; j < 8; j++)
                    acc[i][j] = fmaf(a[i], bb[j], acc[i][j]);
        }
        __syncthreads();
    }

#pragma unroll
    for (int i = 0; i < 8; i++) {
        const size_t r = (size_t)(row0 + tr + i) * G4H + col0 + tc;
#pragma unroll
        for (int j = 0; j < 8; j += 4) {
            float4 o;
            o.x = acc[i][j + 0] + bias[col0 + tc + j + 0];
            o.y = acc[i][j + 1] + bias[col0 + tc + j + 1];
            o.z = acc[i][j + 2] + bias[col0 + tc + j + 2];
            o.w = acc[i][j + 3] + bias[col0 + tc + j + 3];
            *(float4*)&g_G[r + j] = o;
        }
    }
}

// ---------------- kernel 3: cluster-based LSTM recurrence (scalar) -------
// 128 CTAs = 16 clusters of 8 (HW co-schedules each cluster; no deadlock).
// Cluster = one b-block (8 batches); rank = j-block (32 hidden units).
// Thread = (jj 0..31, ke 0..7 k-eighth of 32 k's). Plain scalar FFMA:
// per SM per step = 262144 FMAs -> 4096-cyc fp32-pipe floor, crossbar ~2K cyc
// (1 conflict-free LDS.128 for U + 2 broadcast LDS.128 for h per k).
// h exchanged via DSMEM stores + barrier.cluster each step. ~70 regs.
#define US_FLOATS  32768                     /* float Us[256 k][32 jj][4 g]   */
#define HB_FLOATS  4096                      /* float hbuf[2][256 k][8 b]     */
#define RED_FLOATS 8192                      /* float red[32 r][8 ke][32 jj]  */
#define RSMEM_BYTES ((US_FLOATS + HB_FLOATS + RED_FLOATS) * 4 + 64)  /* 180288 */

__global__ void __launch_bounds__(256, 1) __cluster_dims__(8, 1, 1)
recur_kernel(const float* __restrict__ X,
             const float* __restrict__ U,
             float* __restrict__ out_enc) {
    extern __shared__ float sm[];
    float*    Us   = sm;                       // [k*128 + jj*4 + g]
    float*    hbuf = Us + US_FLOATS;           // [buf*2048 + k*8 + b]
    float*    red  = hbuf + HB_FLOATS;         // [(b*4+g)*256 + ke*32 + jj]
    unsigned* rkb  = (unsigned*)(red + RED_FLOATS);   // [buf][rank] DSMEM bases

    const int tid = threadIdx.x;
    const int jj  = tid & 31;
    const int ke  = tid >> 5;            // k-eighth: k in [ke*32, ke*32+32)
    unsigned rank; asm("mov.u32 %0, %%cluster_ctarank;" : "=r"(rank));
    const int j0 = (int)rank * 32;
    const int b0 = (blockIdx.x >> 3) * 8;

    // ---- load U slice once: Us[k][jj][g] = U[k][g*256 + j0+jj] ----
    for (int idx = tid; idx < US_FLOATS; idx += 256) {
        const int k  = idx >> 7;
        const int jc = (idx >> 2) & 31;
        const int g  = idx & 3;
        Us[idx] = U[(size_t)k * 1024 + g * 256 + j0 + jc];
    }
    // ---- init h0 = c0 = X[b,0,0]; DSMEM base table ----
    for (int idx = tid; idx < 2048; idx += 256) {
        const int b = idx & 7;
        hbuf[idx] = X[(size_t)(b0 + b) * (TM1 * NIN)];
    }
    if (tid < 16) {
        const int buf = tid >> 3, r = tid & 7;
        rkb[tid] = mapa_u32(smem_u32(hbuf + buf * 2048), (unsigned)r);
    }
    // epilogue cell for this thread: (jj, b2)
    const int b2 = tid >> 5;
    const int j2 = j0 + jj;
    float c = X[(size_t)(b0 + b2) * (TM1 * NIN)];
    const unsigned h_off = (unsigned)((j2 * 8 + b2) * 4);  // byte offset in buf

    __syncthreads();
    CLUSTER_SYNC();

    for (int t = 0; t < TM1; t++) {
        // prefetch this step's gate pre-activations (global, coalesced; hides
        // under the 4096-cyc compute)
        const float* grp = g_G + ((size_t)(b0 + b2) * TM1 + t) * G4H + j2;
        const float G0 = grp[0],   G1 = grp[256];
        const float G2 = grp[512], G3 = grp[768];

        // ---- partial h@U over this thread's 32 k values ----
        float acc[8][4];
#pragma unroll
        for (int b = 0; b < 8; b++)
#pragma unroll
            for (int g = 0; g < 4; g++) acc[b][g] = 0.f;

        const float* hb = hbuf + ((t & 1) << 11) + (ke << 8);   // [kl*8 + b]
        const float* up = Us + (ke << 12) + (jj << 2);          // [kl*128 + g]
#pragma unroll 4
        for (int kl = 0; kl < 32; kl++) {
            float u[4], h[8];
            *(float4*)&u[0] = *(const float4*)(up + kl * 128);
            *(float4*)&h[0] = *(const float4*)(hb + kl * 8);
            *(float4*)&h[4] = *(const float4*)(hb + kl * 8 + 4);
#pragma unroll
            for (int b = 0; b < 8; b++)
#pragma unroll
                for (int g = 0; g < 4; g++)
                    acc[b][g] = fmaf(h[b], u[g], acc[b][g]);
        }

        // ---- write k-eighth partials (lanes jj consecutive: conflict-free) --
#pragma unroll
        for (int b = 0; b < 8; b++)
#pragma unroll
            for (int g = 0; g < 4; g++)
                red[(b * 4 + g) * 256 + ke * 32 + jj] = acc[b][g];
        __syncthreads();

        // ---- epilogue: one (j, batch) cell per thread ----
        float z[4];
#pragma unroll
        for (int g = 0; g < 4; g++) {
            const float* rr = red + (b2 * 4 + g) * 256 + jj;
            z[g] = ((rr[0]   + rr[32])  + (rr[64]  + rr[96])) +
                   ((rr[128] + rr[160]) + (rr[192] + rr[224]));
        }
        const float zi = z[0] + G0;
        const float zf = z[1] + G1;
        const float zg = z[2] + G2;
        const float zo = z[3] + G3;

        c = sigm_f(zf) * c + sigm_f(zi) * tanh_f(zg);
        const float hn = sigm_f(zo) * tanh_f(c);

        out_enc[((size_t)(b0 + b2) * TM1 + t) * Hd + j2] = hn;

        // broadcast h_{t+1} to every rank's next buffer (incl. self)
        const unsigned* rkn = rkb + ((t + 1) & 1) * 8;
#pragma unroll
        for (int r = 0; r < 8; r++)
            st_remote_f32(rkn[r] + h_off, hn);

        CLUSTER_SYNC();   // release h writes; acquire before next reads
    }
}

// ---------------- launch ----------------
extern "C" void kernel_launch(void* const* d_in, const int* in_sizes, int n_in,
                              void* d_out, int out_size) {
    const float* X      = (const float*)d_in[0];
    const float* W_attn = (const float*)d_in[1];
    /* b_attn = d_in[2] : cancels in softmax */
    const float* W_lstm = (const float*)d_in[3];
    const float* U_lstm = (const float*)d_in[4];
    const float* b_lstm = (const float*)d_in[5];

    float* out     = (float*)d_out;
    float* out_xt  = out;                             // X_tilde  (B,Tm1,N)
    float* out_enc = out + (size_t)Bsz * TM1 * NIN;   // X_encoded (B,Tm1,H)

    cudaFuncSetAttribute(recur_kernel,
                         cudaFuncAttributeMaxDynamicSharedMemorySize, RSMEM_BYTES);

    alpha_kernel<<<Bsz, 512>>>(X, W_attn, out_xt);
    gemm_kernel<<<dim3(8, TM1), 256>>>(out_xt, W_lstm, b_lstm);
    recur_kernel<<<128, 256, RSMEM_BYTES>>>(X, U_lstm, out_enc);
}

// round 12
// speedup vs baseline: 1.5681x; 1.5681x over previous
#include <cuda_runtime.h>

#define Bsz   128
#define TM1   255
#define NIN   256
#define Hd    256
#define BT    (Bsz * TM1)      /* 32640 */
#define G4H   1024

// ---------------- device scratch (static allocation only) ----------------
__device__ float    g_G[(size_t)BT * G4H];   // 133.7 MB: pre-activations x_tilde@W + b
__device__ float    g_h[2][Bsz * Hd];        // ping-pong hidden state
__device__ unsigned g_bar;                   // grid barrier counter

__global__ void reset_kernel() { g_bar = 0u; }

__device__ __forceinline__ float sigm_f(float x) {
    return 1.0f / (1.0f + __expf(-x));
}
__device__ __forceinline__ float tanh_f(float x) {
    return 2.0f / (1.0f + __expf(-2.0f * x)) - 1.0f;
}

// ---------------- kernel 1: alpha (softmax over inputs) + X_tilde --------
// alpha[b,n] = softmax_n( sum_t X[b,t,n] * W_attn[2H + t] )  (h/c/b_attn terms
// are constant over n and cancel in the softmax). 512 threads: (n, t-half).
// Measured 31.7us in R10.
__global__ __launch_bounds__(512) void alpha_kernel(const float* __restrict__ X,
                                                    const float* __restrict__ W_attn,
                                                    float* __restrict__ out_xt) {
    __shared__ float wx[TM1];
    __shared__ float part[512];
    __shared__ float red[256];
    __shared__ float alph[256];
    const int tid = threadIdx.x;
    const int b   = blockIdx.x;
    const int n   = tid & 255;
    const int th  = tid >> 8;            // t-half: 0 -> [0,128), 1 -> [128,255)
    if (tid < TM1) wx[tid] = W_attn[2 * Hd + tid];
    __syncthreads();

    const float* Xb = X + (size_t)b * TM1 * NIN;
    const int t_lo = th * 128;
    const int t_hi = th ? TM1 : 128;
    float e0 = 0.f, e1 = 0.f, e2 = 0.f, e3 = 0.f;
    int t = t_lo;
#pragma unroll 1
    for (; t + 4 <= t_hi; t += 4) {
        e0 = fmaf(Xb[(t + 0) * NIN + n], wx[t + 0], e0);
        e1 = fmaf(Xb[(t + 1) * NIN + n], wx[t + 1], e1);
        e2 = fmaf(Xb[(t + 2) * NIN + n], wx[t + 2], e2);
        e3 = fmaf(Xb[(t + 3) * NIN + n], wx[t + 3], e3);
    }
    for (; t < t_hi; t++) e0 = fmaf(Xb[t * NIN + n], wx[t], e0);
    part[tid] = (e0 + e1) + (e2 + e3);
    __syncthreads();

    if (tid < 256) {
        float e = part[n] + part[n + 256];
        part[n] = e;          // reuse as per-n e value
        red[n]  = e;
    }
    __syncthreads();
    for (int s = 128; s > 0; s >>= 1) {
        if (tid < s) red[tid] = fmaxf(red[tid], red[tid + s]);
        __syncthreads();
    }
    const float m = red[0];
    __syncthreads();
    if (tid < 256) red[n] = __expf(part[n] - m);
    __syncthreads();
    if (tid < 256) part[n] = red[n];     // keep p
    for (int s = 128; s > 0; s >>= 1) {
        if (tid < s) red[tid] += red[tid + s];
        __syncthreads();
    }
    if (tid < 256) alph[n] = part[n] / red[0];
    __syncthreads();

    const float a = alph[n];
    float* outb = out_xt + (size_t)b * TM1 * NIN;
#pragma unroll 4
    for (int tt = t_lo; tt < t_hi; tt++) outb[tt * NIN + n] = a * Xb[tt * NIN + n];
}

// ---------------- kernel 2: G = X_tilde @ W_lstm + b_lstm ----------------
// Byte-identical logic to the best-measured R4 kernel.
__global__ __launch_bounds__(256, 2) void gemm_kernel(const float* __restrict__ A,
                                                      const float* __restrict__ W,
                                                      const float* __restrict__ bias) {
    __shared__ float As[8][128];
    __shared__ float Bs[8][128];
    const int tid  = threadIdx.x;
    const int row0 = blockIdx.y * 128;
    const int col0 = blockIdx.x * 128;

    float acc[8][8];
#pragma unroll
    for (int i = 0; i < 8; i++)
#pragma unroll
        for (int j = 0; j < 8; j++) acc[i][j] = 0.f;

    const int tr = (tid >> 4) << 3;
    const int tc = (tid & 15) << 3;
    const int am = tid >> 1,  ak = (tid & 1) << 2;
    const int bk = tid >> 5,  bc = (tid & 31) << 2;

    for (int k0 = 0; k0 < 256; k0 += 8) {
        float4 av = *(const float4*)(A + (size_t)(row0 + am) * 256 + k0 + ak);
        As[ak + 0][am] = av.x; As[ak + 1][am] = av.y;
        As[ak + 2][am] = av.z; As[ak + 3][am] = av.w;
        float4 bv = *(const float4*)(W + (size_t)(k0 + bk) * 1024 + col0 + bc);
        *(float4*)&Bs[bk][bc] = bv;
        __syncthreads();
#pragma unroll
        for (int k = 0; k < 8; k++) {
            float a[8], bb[8];
            *(float4*)&a[0]  = *(const float4*)&As[k][tr];
            *(float4*)&a[4]  = *(const float4*)&As[k][tr + 4];
            *(float4*)&bb[0] = *(const float4*)&Bs[k][tc];
            *(float4*)&bb[4] = *(const float4*)&Bs[k][tc + 4];
#pragma unroll
            for (int i = 0; i < 8; i++)
#pragma unroll
                for (int j = 0; j < 8; j++)
                    acc[i][j] = fmaf(a[i], bb[j], acc[i][j]);
        }
        __syncthreads();
    }

#pragma unroll
    for (int i = 0; i < 8; i++) {
        const size_t r = (size_t)(row0 + tr + i) * G4H + col0 + tc;
#pragma unroll
        for (int j = 0; j < 8; j += 4) {
            float4 o;
            o.x = acc[i][j + 0] + bias[col0 + tc + j + 0];
            o.y = acc[i][j + 1] + bias[col0 + tc + j + 1];
            o.z = acc[i][j + 2] + bias[col0 + tc + j + 2];
            o.w = acc[i][j + 3] + bias[col0 + tc + j + 3];
            *(float4*)&g_G[r + j] = o;
        }
    }
}

// ---------------- kernel 3: persistent LSTM recurrence -------------------
// EXACTLY the R4 design (best measured) with ONE change: 256 threads instead
// of 128 — the k dimension is split in half across kh = tid>>7, doubling
// warps/SMSP from 1 to 2 to hide LDS/FFMA latency (R4 profile: issue=22%).
// Partial sums of the two k-halves merge through a 4 KB smem buffer.
// Grid = 128 CTAs, 1 CTA/SM (143 KB smem) => all co-resident, safe barrier.
#define RCTAS    128
#define RTHREADS 256
#define RSMEM    (256 * 32 * 16 + 8 * 256 * 4 + 8 * 128 * 4)  /* 143360 B */

__global__ void __launch_bounds__(RTHREADS, 1)
recur_kernel(const float* __restrict__ X,
             const float* __restrict__ U,
             float* __restrict__ out_enc) {
    extern __shared__ float4 smem4[];
    float4* Us4 = smem4;                    // [256k][32jj]: (i,f,g,o) per (k,j)
    float4* hs4 = smem4 + 256 * 32;         // [8 b][64]: 8 batch rows x 256 h
    float*  red = (float*)(smem4 + 256 * 32 + 8 * 64);  // [8 acc][128 cell]

    const int tid  = threadIdx.x;
    const int cta  = blockIdx.x;
    const int b0   = (cta & 15) * 8;        // 16 b-blocks
    const int j0   = (cta >> 4) * 32;       // 8 j-blocks
    const int jj   = tid & 31;
    const int bs   = (tid >> 5) & 3;        // 0..3
    const int kh   = tid >> 7;              // k-half: [kh*128, kh*128+128)
    const int j    = j0 + jj;
    const int b_a  = b0 + bs;
    const int b_b  = b0 + bs + 4;
    const int cell = tid & 127;             // (bs,jj) cell id

    // Load U slice once: Us4[k*32+jj] = (U[k][j], U[k][256+j], U[k][512+j], U[k][768+j])
    for (int idx = tid; idx < 256 * 32; idx += RTHREADS) {
        const int k  = idx >> 5;
        const int jc = j0 + (idx & 31);
        const float* Uk = U + (size_t)k * 1024;
        Us4[idx] = make_float4(Uk[jc], Uk[256 + jc], Uk[512 + jc], Uk[768 + jc]);
    }

    // init: h0 = c0 = X[b,0,0] broadcast over hidden dim
    const float x00a = X[(size_t)b_a * (TM1 * NIN)];
    const float x00b = X[(size_t)b_b * (TM1 * NIN)];
    if (kh == 0) {
        g_h[0][b_a * Hd + j] = x00a;
        g_h[0][b_b * Hd + j] = x00b;
    }
    float ca = x00a, cb = x00b;
    __threadfence();
    __syncthreads();
    if (tid == 0) atomicAdd(&g_bar, 1u);

    volatile unsigned* barp = &g_bar;

    for (int t = 0; t < TM1; t++) {
        // wait for all h writes of previous phase
        if (tid == 0) {
            const unsigned target = (unsigned)(t + 1) * RCTAS;
            while (*barp < target) { }
            __threadfence();
        }
        __syncthreads();

        // stage h rows b0..b0+7 into smem
        const float4* hsrc = (const float4*)(g_h[t & 1] + b0 * Hd);
        for (int i = tid; i < 8 * 64; i += RTHREADS) hs4[i] = hsrc[i];
        __syncthreads();

        // gate pre-activations from G (only the kh==0 half needs them)
        float ai, af, ag, ao, bi, bf, bg, bo;
        if (kh == 0) {
            const size_t rowa = ((size_t)b_a * TM1 + t) * G4H;
            const size_t rowb = ((size_t)b_b * TM1 + t) * G4H;
            ai = g_G[rowa + j];       af = g_G[rowa + 256 + j];
            ag = g_G[rowa + 512 + j]; ao = g_G[rowa + 768 + j];
            bi = g_G[rowb + j];       bf = g_G[rowb + 256 + j];
            bg = g_G[rowb + 512 + j]; bo = g_G[rowb + 768 + j];
        } else {
            ai = af = ag = ao = bi = bf = bg = bo = 0.f;
        }

        // h @ U over this thread's k-half (32 iterations of 4 k's)
        const float4* ha4 = hs4 + bs * 64 + kh * 32;
        const float4* hb4 = hs4 + (bs + 4) * 64 + kh * 32;
        const float4* up  = Us4 + (kh * 128) * 32 + jj;
#pragma unroll 4
        for (int m = 0; m < 32; m++) {
            const float4 ha = ha4[m];
            const float4 hb = hb4[m];
            float4 u;
            u = up[(4 * m + 0) * 32];
            ai = fmaf(ha.x, u.x, ai); af = fmaf(ha.x, u.y, af);
            ag = fmaf(ha.x, u.z, ag); ao = fmaf(ha.x, u.w, ao);
            bi = fmaf(hb.x, u.x, bi); bf = fmaf(hb.x, u.y, bf);
            bg = fmaf(hb.x, u.z, bg); bo = fmaf(hb.x, u.w, bo);
            u = up[(4 * m + 1) * 32];
            ai = fmaf(ha.y, u.x, ai); af = fmaf(ha.y, u.y, af);
            ag = fmaf(ha.y, u.z, ag); ao = fmaf(ha.y, u.w, ao);
            bi = fmaf(hb.y, u.x, bi); bf = fmaf(hb.y, u.y, bf);
            bg = fmaf(hb.y, u.z, bg); bo = fmaf(hb.y, u.w, bo);
            u = up[(4 * m + 2) * 32];
            ai = fmaf(ha.z, u.x, ai); af = fmaf(ha.z, u.y, af);
            ag = fmaf(ha.z, u.z, ag); ao = fmaf(ha.z, u.w, ao);
            bi = fmaf(hb.z, u.x, bi); bf = fmaf(hb.z, u.y, bf);
            bg = fmaf(hb.z, u.z, bg); bo = fmaf(hb.z, u.w, bo);
            u = up[(4 * m + 3) * 32];
            ai = fmaf(ha.w, u.x, ai); af = fmaf(ha.w, u.y, af);
            ag = fmaf(ha.w, u.z, ag); ao = fmaf(ha.w, u.w, ao);
            bi = fmaf(hb.w, u.x, bi); bf = fmaf(hb.w, u.y, bf);
            bg = fmaf(hb.w, u.z, bg); bo = fmaf(hb.w, u.w, bo);
        }

        // merge the two k-halves (conflict-free: lanes consecutive per row)
        if (kh == 1) {
            red[0 * 128 + cell] = ai; red[1 * 128 + cell] = af;
            red[2 * 128 + cell] = ag; red[3 * 128 + cell] = ao;
            red[4 * 128 + cell] = bi; red[5 * 128 + cell] = bf;
            red[6 * 128 + cell] = bg; red[7 * 128 + cell] = bo;
        }
        __syncthreads();

        if (kh == 0) {
            ai += red[0 * 128 + cell]; af += red[1 * 128 + cell];
            ag += red[2 * 128 + cell]; ao += red[3 * 128 + cell];
            bi += red[4 * 128 + cell]; bf += red[5 * 128 + cell];
            bg += red[6 * 128 + cell]; bo += red[7 * 128 + cell];

            // LSTM cell (Keras gate order i,f,g,o)
            ca = sigm_f(af) * ca + sigm_f(ai) * tanh_f(ag);
            const float hna = sigm_f(ao) * tanh_f(ca);
            cb = sigm_f(bf) * cb + sigm_f(bi) * tanh_f(bg);
            const float hnb = sigm_f(bo) * tanh_f(cb);

            g_h[(t + 1) & 1][b_a * Hd + j] = hna;
            g_h[(t + 1) & 1][b_b * Hd + j] = hnb;
            out_enc[((size_t)b_a * TM1 + t) * Hd + j] = hna;
            out_enc[((size_t)b_b * TM1 + t) * Hd + j] = hnb;
        }

        __threadfence();
        __syncthreads();
        if (tid == 0) atomicAdd(&g_bar, 1u);
    }
}

// ---------------- launch ----------------
extern "C" void kernel_launch(void* const* d_in, const int* in_sizes, int n_in,
                              void* d_out, int out_size) {
    const float* X      = (const float*)d_in[0];
    const float* W_attn = (const float*)d_in[1];
    /* b_attn = d_in[2] : cancels in softmax */
    const float* W_lstm = (const float*)d_in[3];
    const float* U_lstm = (const float*)d_in[4];
    const float* b_lstm = (const float*)d_in[5];

    float* out     = (float*)d_out;
    float* out_xt  = out;                             // X_tilde  (B,Tm1,N)
    float* out_enc = out + (size_t)Bsz * TM1 * NIN;   // X_encoded (B,Tm1,H)

    cudaFuncSetAttribute(recur_kernel,
                         cudaFuncAttributeMaxDynamicSharedMemorySize, RSMEM);

    reset_kernel<<<1, 1>>>();
    alpha_kernel<<<Bsz, 512>>>(X, W_attn, out_xt);
    gemm_kernel<<<dim3(8, TM1), 256>>>(out_xt, W_lstm, b_lstm);
    recur_kernel<<<RCTAS, RTHREADS, RSMEM>>>(X, U_lstm, out_enc);
}

// round 13
// speedup vs baseline: 1.7826x; 1.1367x over previous
#include <cuda_runtime.h>

#define Bsz   128
#define TM1   255
#define NIN   256
#define Hd    256
#define BT    (Bsz * TM1)      /* 32640 */
#define G4H   1024

// ---------------- device scratch (static allocation only) ----------------
__device__ float    g_G[(size_t)BT * G4H];   // 133.7 MB: pre-activations x_tilde@W + b
__device__ float    g_h[2][Bsz * Hd];        // ping-pong hidden state
__device__ unsigned g_bar;                   // grid barrier counter

__global__ void reset_kernel() { g_bar = 0u; }

__device__ __forceinline__ float sigm_f(float x) {
    return 1.0f / (1.0f + __expf(-x));
}
__device__ __forceinline__ float tanh_f(float x) {
    return 2.0f / (1.0f + __expf(-2.0f * x)) - 1.0f;
}

// ---------------- kernel 1: alpha (softmax over inputs) + X_tilde --------
// alpha[b,n] = softmax_n( sum_t X[b,t,n] * W_attn[2H + t] )  (h/c/b_attn terms
// are constant over n and cancel in the softmax). Measured 31.7us.
__global__ __launch_bounds__(512) void alpha_kernel(const float* __restrict__ X,
                                                    const float* __restrict__ W_attn,
                                                    float* __restrict__ out_xt) {
    __shared__ float wx[TM1];
    __shared__ float part[512];
    __shared__ float red[256];
    __shared__ float alph[256];
    const int tid = threadIdx.x;
    const int b   = blockIdx.x;
    const int n   = tid & 255;
    const int th  = tid >> 8;            // t-half: 0 -> [0,128), 1 -> [128,255)
    if (tid < TM1) wx[tid] = W_attn[2 * Hd + tid];
    __syncthreads();

    const float* Xb = X + (size_t)b * TM1 * NIN;
    const int t_lo = th * 128;
    const int t_hi = th ? TM1 : 128;
    float e0 = 0.f, e1 = 0.f, e2 = 0.f, e3 = 0.f;
    int t = t_lo;
#pragma unroll 1
    for (; t + 4 <= t_hi; t += 4) {
        e0 = fmaf(Xb[(t + 0) * NIN + n], wx[t + 0], e0);
        e1 = fmaf(Xb[(t + 1) * NIN + n], wx[t + 1], e1);
        e2 = fmaf(Xb[(t + 2) * NIN + n], wx[t + 2], e2);
        e3 = fmaf(Xb[(t + 3) * NIN + n], wx[t + 3], e3);
    }
    for (; t < t_hi; t++) e0 = fmaf(Xb[t * NIN + n], wx[t], e0);
    part[tid] = (e0 + e1) + (e2 + e3);
    __syncthreads();

    if (tid < 256) {
        float e = part[n] + part[n + 256];
        part[n] = e;
        red[n]  = e;
    }
    __syncthreads();
    for (int s = 128; s > 0; s >>= 1) {
        if (tid < s) red[tid] = fmaxf(red[tid], red[tid + s]);
        __syncthreads();
    }
    const float m = red[0];
    __syncthreads();
    if (tid < 256) red[n] = __expf(part[n] - m);
    __syncthreads();
    if (tid < 256) part[n] = red[n];
    for (int s = 128; s > 0; s >>= 1) {
        if (tid < s) red[tid] += red[tid + s];
        __syncthreads();
    }
    if (tid < 256) alph[n] = part[n] / red[0];
    __syncthreads();

    const float a = alph[n];
    float* outb = out_xt + (size_t)b * TM1 * NIN;
#pragma unroll 4
    for (int tt = t_lo; tt < t_hi; tt++) outb[tt * NIN + n] = a * Xb[tt * NIN + n];
}

// ---------------- kernel 2: G = X_tilde @ W_lstm + b_lstm ----------------
// Byte-identical logic to the best-measured R4 kernel.
__global__ __launch_bounds__(256, 2) void gemm_kernel(const float* __restrict__ A,
                                                      const float* __restrict__ W,
                                                      const float* __restrict__ bias) {
    __shared__ float As[8][128];
    __shared__ float Bs[8][128];
    const int tid  = threadIdx.x;
    const int row0 = blockIdx.y * 128;
    const int col0 = blockIdx.x * 128;

    float acc[8][8];
#pragma unroll
    for (int i = 0; i < 8; i++)
#pragma unroll
        for (int j = 0; j < 8; j++) acc[i][j] = 0.f;

    const int tr = (tid >> 4) << 3;
    const int tc = (tid & 15) << 3;
    const int am = tid >> 1,  ak = (tid & 1) << 2;
    const int bk = tid >> 5,  bc = (tid & 31) << 2;

    for (int k0 = 0; k0 < 256; k0 += 8) {
        float4 av = *(const float4*)(A + (size_t)(row0 + am) * 256 + k0 + ak);
        As[ak + 0][am] = av.x; As[ak + 1][am] = av.y;
        As[ak + 2][am] = av.z; As[ak + 3][am] = av.w;
        float4 bv = *(const float4*)(W + (size_t)(k0 + bk) * 1024 + col0 + bc);
        *(float4*)&Bs[bk][bc] = bv;
        __syncthreads();
#pragma unroll
        for (int k = 0; k < 8; k++) {
            float a[8], bb[8];
            *(float4*)&a[0]  = *(const float4*)&As[k][tr];
            *(float4*)&a[4]  = *(const float4*)&As[k][tr + 4];
            *(float4*)&bb[0] = *(const float4*)&Bs[k][tc];
            *(float4*)&bb[4] = *(const float4*)&Bs[k][tc + 4];
#pragma unroll
            for (int i = 0; i < 8; i++)
#pragma unroll
                for (int j = 0; j < 8; j++)
                    acc[i][j] = fmaf(a[i], bb[j], acc[i][j]);
        }
        __syncthreads();
    }

#pragma unroll
    for (int i = 0; i < 8; i++) {
        const size_t r = (size_t)(row0 + tr + i) * G4H + col0 + tc;
#pragma unroll
        for (int j = 0; j < 8; j += 4) {
            float4 o;
            o.x = acc[i][j + 0] + bias[col0 + tc + j + 0];
            o.y = acc[i][j + 1] + bias[col0 + tc + j + 1];
            o.z = acc[i][j + 2] + bias[col0 + tc + j + 2];
            o.w = acc[i][j + 3] + bias[col0 + tc + j + 3];
            *(float4*)&g_G[r + j] = o;
        }
    }
}

// ---------------- kernel 3: persistent LSTM recurrence -------------------
// 128 CTAs (1/SM, co-resident, proven global-atomic barrier). CTA owns
// (b-block of 8, j-block of 32). 512 threads = (jj 0..31, ke 0..15); each
// thread covers ALL 8 batches over its 16 k's: one U float4 feeds 32 FMAs
// (4x less U crossbar than R12), h loads are warp-broadcast. Partials merge
// through a padded 64 KB smem reduction; epilogue = 1 cell/thread (tid<256).
#define RCTAS    128
#define RTHREADS 512
#define US_F4    (256 * 32)                   /* float4 Us[k][jj]    128 KB  */
#define HS_F4    (256 * 2)                    /* float4 hs[k][2]       8 KB  */
#define RED_F4   (16 * 8 * 32)                /* float4 red[ke][b][jj] 64 KB */
#define RSMEM    ((US_F4 + HS_F4 + RED_F4) * 16)          /* 204800 B        */

__global__ void __launch_bounds__(RTHREADS, 1)
recur_kernel(const float* __restrict__ X,
             const float* __restrict__ U,
             float* __restrict__ out_enc) {
    extern __shared__ float4 smem4[];
    float4* Us4  = smem4;                     // [k*32 + jj] = gates i,f,g,o
    float4* hs4  = smem4 + US_F4;             // [k*2 + half] = h[k][b0..b7]
    float4* red4 = smem4 + US_F4 + HS_F4;     // [(ke*8 + b)*32 + jj]

    const int tid = threadIdx.x;
    const int cta = blockIdx.x;
    const int b0  = (cta & 15) * 8;           // 16 b-blocks
    const int j0  = (cta >> 4) * 32;          // 8 j-blocks
    const int jj  = tid & 31;
    const int ke  = tid >> 5;                 // k-16th: [ke*16, ke*16+16)

    // ---- load U slice once: Us4[k*32+jj] = (U[k][j], U[k][256+j], ...) ----
    for (int idx = tid; idx < US_F4; idx += RTHREADS) {
        const int k  = idx >> 5;
        const int jc = j0 + (idx & 31);
        const float* Uk = U + (size_t)k * 1024;
        Us4[idx] = make_float4(Uk[jc], Uk[256 + jc], Uk[512 + jc], Uk[768 + jc]);
    }

    // epilogue cell for threads tid<256: (jj, b2)
    const int b2 = tid >> 5;                  // valid for tid<256: 0..7
    const int j2 = j0 + jj;
    float c = 0.f;
    if (tid < 256) {
        const float x0 = X[(size_t)(b0 + b2) * (TM1 * NIN)];
        c = x0;
        g_h[0][(b0 + b2) * Hd + j2] = x0;     // h0 broadcast over hidden dim
    }
    __threadfence();
    __syncthreads();
    if (tid == 0) atomicAdd(&g_bar, 1u);

    volatile unsigned* barp = &g_bar;

    for (int t = 0; t < TM1; t++) {
        // ---- wait for all h_t writes ----
        if (tid == 0) {
            const unsigned target = (unsigned)(t + 1) * RCTAS;
            while (*barp < target) { }
            __threadfence();
        }
        __syncthreads();

        // ---- prefetch this step's G (issue early; latency hides) ----
        float G0, G1, G2, G3;
        if (tid < 256) {
            const float* grp = g_G + ((size_t)(b0 + b2) * TM1 + t) * G4H + j2;
            G0 = grp[0];   G1 = grp[256];
            G2 = grp[512], G3 = grp[768];
        }

        // ---- stage h_t transposed: hs[k][b] ; thread tid<256 owns k=tid ----
        if (tid < 256) {
            const int k = tid;                // warp lanes: consecutive k
            const float* hsrc = g_h[t & 1] + b0 * Hd + k;
            float4 lo, hi;                    // coalesced LDG per b
            lo.x = hsrc[0 * Hd]; lo.y = hsrc[1 * Hd];
            lo.z = hsrc[2 * Hd]; lo.w = hsrc[3 * Hd];
            hi.x = hsrc[4 * Hd]; hi.y = hsrc[5 * Hd];
            hi.z = hsrc[6 * Hd]; hi.w = hsrc[7 * Hd];
            hs4[k * 2]     = lo;              // STS.128, lane-consecutive
            hs4[k * 2 + 1] = hi;
        }
        __syncthreads();

        // ---- partial h@U over this thread's 16 k values, all 8 batches ----
        float acc[8][4];
#pragma unroll
        for (int b = 0; b < 8; b++)
#pragma unroll
            for (int g = 0; g < 4; g++) acc[b][g] = 0.f;

        const float4* up = Us4 + (ke * 16) * 32 + jj;
        const float4* hp = hs4 + (ke * 16) * 2;
#pragma unroll 4
        for (int kl = 0; kl < 16; kl++) {
            const float4 u  = up[kl * 32];    // 1 LDS.128 -> 32 FMAs
            const float4 h0 = hp[kl * 2];     // broadcast
            const float4 h1 = hp[kl * 2 + 1]; // broadcast
            acc[0][0] = fmaf(h0.x, u.x, acc[0][0]); acc[0][1] = fmaf(h0.x, u.y, acc[0][1]);
            acc[0][2] = fmaf(h0.x, u.z, acc[0][2]); acc[0][3] = fmaf(h0.x, u.w, acc[0][3]);
            acc[1][0] = fmaf(h0.y, u.x, acc[1][0]); acc[1][1] = fmaf(h0.y, u.y, acc[1][1]);
            acc[1][2] = fmaf(h0.y, u.z, acc[1][2]); acc[1][3] = fmaf(h0.y, u.w, acc[1][3]);
            acc[2][0] = fmaf(h0.z, u.x, acc[2][0]); acc[2][1] = fmaf(h0.z, u.y, acc[2][1]);
            acc[2][2] = fmaf(h0.z, u.z, acc[2][2]); acc[2][3] = fmaf(h0.z, u.w, acc[2][3]);
            acc[3][0] = fmaf(h0.w, u.x, acc[3][0]); acc[3][1] = fmaf(h0.w, u.y, acc[3][1]);
            acc[3][2] = fmaf(h0.w, u.z, acc[3][2]); acc[3][3] = fmaf(h0.w, u.w, acc[3][3]);
            acc[4][0] = fmaf(h1.x, u.x, acc[4][0]); acc[4][1] = fmaf(h1.x, u.y, acc[4][1]);
            acc[4][2] = fmaf(h1.x, u.z, acc[4][2]); acc[4][3] = fmaf(h1.x, u.w, acc[4][3]);
            acc[5][0] = fmaf(h1.y, u.x, acc[5][0]); acc[5][1] = fmaf(h1.y, u.y, acc[5][1]);
            acc[5][2] = fmaf(h1.y, u.z, acc[5][2]); acc[5][3] = fmaf(h1.y, u.w, acc[5][3]);
            acc[6][0] = fmaf(h1.z, u.x, acc[6][0]); acc[6][1] = fmaf(h1.z, u.y, acc[6][1]);
            acc[6][2] = fmaf(h1.z, u.z, acc[6][2]); acc[6][3] = fmaf(h1.z, u.w, acc[6][3]);
            acc[7][0] = fmaf(h1.w, u.x, acc[7][0]); acc[7][1] = fmaf(h1.w, u.y, acc[7][1]);
            acc[7][2] = fmaf(h1.w, u.z, acc[7][2]); acc[7][3] = fmaf(h1.w, u.w, acc[7][3]);
        }

        // ---- write k-16th partials: red4[(ke*8 + b)*32 + jj] ----
        {
            float4* rw = red4 + (ke * 8) * 32 + jj;
#pragma unroll
            for (int b = 0; b < 8; b++)
                rw[b * 32] = make_float4(acc[b][0], acc[b][1], acc[b][2], acc[b][3]);
        }
        __syncthreads();

        // ---- epilogue: one (j, batch) cell per thread (tid<256) ----
        if (tid < 256) {
            const float4* rr = red4 + b2 * 32 + jj;
            float4 s0 = rr[0];
#pragma unroll
            for (int k16 = 1; k16 < 16; k16++) {
                const float4 p = rr[k16 * 8 * 32];
                s0.x += p.x; s0.y += p.y; s0.z += p.z; s0.w += p.w;
            }
            const float zi = s0.x + G0;
            const float zf = s0.y + G1;
            const float zg = s0.z + G2;
            const float zo = s0.w + G3;

            c = sigm_f(zf) * c + sigm_f(zi) * tanh_f(zg);
            const float hn = sigm_f(zo) * tanh_f(c);

            g_h[(t + 1) & 1][(b0 + b2) * Hd + j2] = hn;
            out_enc[((size_t)(b0 + b2) * TM1 + t) * Hd + j2] = hn;
            __threadfence();                  // release h writes (writers only)
        }
        __syncthreads();
        if (tid == 0) atomicAdd(&g_bar, 1u);
    }
}

// ---------------- launch ----------------
extern "C" void kernel_launch(void* const* d_in, const int* in_sizes, int n_in,
                              void* d_out, int out_size) {
    const float* X      = (const float*)d_in[0];
    const float* W_attn = (const float*)d_in[1];
    /* b_attn = d_in[2] : cancels in softmax */
    const float* W_lstm = (const float*)d_in[3];
    const float* U_lstm = (const float*)d_in[4];
    const float* b_lstm = (const float*)d_in[5];

    float* out     = (float*)d_out;
    float* out_xt  = out;                             // X_tilde  (B,Tm1,N)
    float* out_enc = out + (size_t)Bsz * TM1 * NIN;   // X_encoded (B,Tm1,H)

    cudaFuncSetAttribute(recur_kernel,
                         cudaFuncAttributeMaxDynamicSharedMemorySize, RSMEM);

    reset_kernel<<<1, 1>>>();
    alpha_kernel<<<Bsz, 512>>>(X, W_attn, out_xt);
    gemm_kernel<<<dim3(8, TM1), 256>>>(out_xt, W_lstm, b_lstm);
    recur_kernel<<<RCTAS, RTHREADS, RSMEM>>>(X, U_lstm, out_enc);
}

// round 15
// speedup vs baseline: 2.0635x; 1.1576x over previous
#include <cuda_runtime.h>
#include <cuda_bf16.h>

typedef unsigned long long ull;

#define Bsz   128
#define TM1   255
#define NIN   256
#define Hd    256
#define BT    (Bsz * TM1)      /* 32640 */
#define G4H   1024

// ---------------- device scratch (static allocation only) ----------------
__device__ float    g_G[(size_t)BT * G4H];    // 133.7 MB: x_tilde@W + b
__device__ float    g_h[2][Bsz * Hd];         // ping-pong hidden state
__device__ unsigned g_barg[16 * 32];          // per-b-group barrier counters
__device__ __align__(16) __nv_bfloat16 g_Ah[(size_t)BT * NIN];   // x_tilde hi
__device__ __align__(16) __nv_bfloat16 g_Al[(size_t)BT * NIN];   // x_tilde lo
__device__ __align__(16) __nv_bfloat16 g_Wh[(size_t)G4H * NIN];  // W^T hi [n][k]
__device__ __align__(16) __nv_bfloat16 g_Wl[(size_t)G4H * NIN];  // W^T lo

__global__ void reset_kernel() {
    if (threadIdx.x < 16 * 32) g_barg[threadIdx.x] = 0u;
}

__device__ __forceinline__ float sigm_f(float x) { return 1.0f / (1.0f + __expf(-x)); }
__device__ __forceinline__ float tanh_f(float x) { return 2.0f / (1.0f + __expf(-2.0f * x)) - 1.0f; }

__device__ __forceinline__ unsigned smem_u32(const void* p) {
    unsigned r;
    asm("{ .reg .u64 t; cvta.to.shared.u64 t, %1; cvt.u32.u64 %0, t; }" : "=r"(r) : "l"(p));
    return r;
}
__device__ __forceinline__ void ldm_x4(unsigned& r0, unsigned& r1, unsigned& r2,
                                       unsigned& r3, unsigned addr) {
    asm volatile("ldmatrix.sync.aligned.m8n8.x4.shared.b16 {%0,%1,%2,%3}, [%4];"
                 : "=r"(r0), "=r"(r1), "=r"(r2), "=r"(r3) : "r"(addr));
}
__device__ __forceinline__ void mma16816(float* c, const unsigned* a, const unsigned* b) {
    asm volatile(
        "mma.sync.aligned.m16n8k16.row.col.f32.bf16.bf16.f32 "
        "{%0,%1,%2,%3}, {%4,%5,%6,%7}, {%8,%9}, {%0,%1,%2,%3};"
        : "+f"(c[0]), "+f"(c[1]), "+f"(c[2]), "+f"(c[3])
        : "r"(a[0]), "r"(a[1]), "r"(a[2]), "r"(a[3]), "r"(b[0]), "r"(b[1]));
}

// ---------------- kernel 1: alpha (softmax over inputs) + X_tilde --------
__global__ __launch_bounds__(512) void alpha_kernel(const float* __restrict__ X,
                                                    const float* __restrict__ W_attn,
                                                    float* __restrict__ out_xt) {
    __shared__ float wx[TM1];
    __shared__ float part[512];
    __shared__ float red[256];
    __shared__ float alph[256];
    const int tid = threadIdx.x;
    const int b   = blockIdx.x;
    const int n   = tid & 255;
    const int th  = tid >> 8;
    if (tid < TM1) wx[tid] = W_attn[2 * Hd + tid];
    __syncthreads();

    const float* Xb = X + (size_t)b * TM1 * NIN;
    const int t_lo = th * 128;
    const int t_hi = th ? TM1 : 128;
    float e0 = 0.f, e1 = 0.f, e2 = 0.f, e3 = 0.f;
    int t = t_lo;
#pragma unroll 1
    for (; t + 4 <= t_hi; t += 4) {
        e0 = fmaf(Xb[(t + 0) * NIN + n], wx[t + 0], e0);
        e1 = fmaf(Xb[(t + 1) * NIN + n], wx[t + 1], e1);
        e2 = fmaf(Xb[(t + 2) * NIN + n], wx[t + 2], e2);
        e3 = fmaf(Xb[(t + 3) * NIN + n], wx[t + 3], e3);
    }
    for (; t < t_hi; t++) e0 = fmaf(Xb[t * NIN + n], wx[t], e0);
    part[tid] = (e0 + e1) + (e2 + e3);
    __syncthreads();

    if (tid < 256) { float e = part[n] + part[n + 256]; part[n] = e; red[n] = e; }
    __syncthreads();
    for (int s = 128; s > 0; s >>= 1) {
        if (tid < s) red[tid] = fmaxf(red[tid], red[tid + s]);
        __syncthreads();
    }
    const float m = red[0];
    __syncthreads();
    if (tid < 256) red[n] = __expf(part[n] - m);
    __syncthreads();
    if (tid < 256) part[n] = red[n];
    for (int s = 128; s > 0; s >>= 1) {
        if (tid < s) red[tid] += red[tid + s];
        __syncthreads();
    }
    if (tid < 256) alph[n] = part[n] / red[0];
    __syncthreads();

    const float a = alph[n];
    float* outb = out_xt + (size_t)b * TM1 * NIN;
#pragma unroll 4
    for (int tt = t_lo; tt < t_hi; tt++) outb[tt * NIN + n] = a * Xb[tt * NIN + n];
}

// ---------------- conversion kernels (fp32 -> bf16 hi/lo split) ----------
__global__ __launch_bounds__(256) void convA_kernel(const float* __restrict__ src) {
    const size_t i4 = (size_t)blockIdx.x * 256 + threadIdx.x;   // 4 floats each
    float4 v = *(const float4*)(src + i4 * 4);
    __nv_bfloat16 h0 = __float2bfloat16(v.x), h1 = __float2bfloat16(v.y);
    __nv_bfloat16 h2 = __float2bfloat16(v.z), h3 = __float2bfloat16(v.w);
    __nv_bfloat16 l0 = __float2bfloat16(v.x - __bfloat162float(h0));
    __nv_bfloat16 l1 = __float2bfloat16(v.y - __bfloat162float(h1));
    __nv_bfloat16 l2 = __float2bfloat16(v.z - __bfloat162float(h2));
    __nv_bfloat16 l3 = __float2bfloat16(v.w - __bfloat162float(h3));
    unsigned short hs[4] = { *(unsigned short*)&h0, *(unsigned short*)&h1,
                             *(unsigned short*)&h2, *(unsigned short*)&h3 };
    unsigned short ls[4] = { *(unsigned short*)&l0, *(unsigned short*)&l1,
                             *(unsigned short*)&l2, *(unsigned short*)&l3 };
    *(ull*)(g_Ah + i4 * 4) = *(ull*)hs;
    *(ull*)(g_Al + i4 * 4) = *(ull*)ls;
}

__global__ __launch_bounds__(256) void convW_kernel(const float* __restrict__ W) {
    const int n = blockIdx.x;          // 0..1023
    const int k = threadIdx.x;         // 0..255
    const float v = W[(size_t)k * G4H + n];
    const __nv_bfloat16 h = __float2bfloat16(v);
    const __nv_bfloat16 l = __float2bfloat16(v - __bfloat162float(h));
    g_Wh[(size_t)n * NIN + k] = h;
    g_Wl[(size_t)n * NIN + k] = l;
}

// ---------------- kernel 2: G = X_tilde @ W + b via mma.sync bf16-split --
// CTA 128x128, 8 warps (2x4), warp tile 64x32 (4 m16-tiles x 4 n8-tiles).
// K chunked by 64 into SW128 smem (128B rows -> swizzle = col ^ ((row&7)<<4)).
// Passes Ah@Bh + Ah@Bl + Al@Bh accumulate in the same fp32 fragments.
#define GC_SMEM 65536
__global__ __launch_bounds__(256) void gemm_tc_kernel(const float* __restrict__ bias) {
    extern __shared__ char smem[];
    const unsigned sb = smem_u32(smem);
    const unsigned AsH = sb, AsL = sb + 16384, BsH = sb + 32768, BsL = sb + 49152;
    const int tid  = threadIdx.x;
    const int wid  = tid >> 5;
    const int lane = tid & 31;
    const int wm   = wid >> 2;            // 0..1  (64-row band)
    const int wn   = wid & 3;             // 0..3  (32-col band)
    const int row0 = blockIdx.y * 128;
    const int col0 = blockIdx.x * 128;

    float acc[4][4][4];
#pragma unroll
    for (int mt = 0; mt < 4; mt++)
#pragma unroll
        for (int nt = 0; nt < 4; nt++)
#pragma unroll
            for (int i = 0; i < 4; i++) acc[mt][nt][i] = 0.f;

    // per-lane ldmatrix address components
    const int      rin  = lane & 7;
    const unsigned rx   = (unsigned)(rin << 4);
    const unsigned aRow = (unsigned)((rin + ((lane >> 3) & 1) * 8) * 128);
    const unsigned aKq  = (unsigned)((lane >> 4) * 16);
    const unsigned bRow = (unsigned)((rin + (lane >> 4) * 8) * 128);
    const unsigned bKq  = (unsigned)(((lane >> 3) & 1) * 16);

    for (int ch = 0; ch < 4; ch++) {
        const int kc = ch * 64;
        // ---- stage chunk: A 128x64 (h,l) + B 128x64 (h,l), swizzled ----
        for (int idx = tid; idx < 1024; idx += 256) {
            const int r = idx >> 3, jb = (idx & 7) * 16;
            const unsigned d = (unsigned)(r * 128 + (jb ^ ((r & 7) << 4)));
            const size_t ga = (size_t)(row0 + r) * NIN + kc + (idx & 7) * 8;
            const size_t gb = (size_t)(col0 + r) * NIN + kc + (idx & 7) * 8;
            *(uint4*)(smem + d)         = *(const uint4*)(g_Ah + ga);
            *(uint4*)(smem + 16384 + d) = *(const uint4*)(g_Al + ga);
            *(uint4*)(smem + 32768 + d) = *(const uint4*)(g_Wh + gb);
            *(uint4*)(smem + 49152 + d) = *(const uint4*)(g_Wl + gb);
        }
        __syncthreads();

#pragma unroll
        for (int ks = 0; ks < 4; ks++) {
            const unsigned cb = (unsigned)(ks * 32);   // byte col of k-step
            // ---- B fragments: 4 n8-tiles, hi and lo ----
            unsigned bh[4][2], bl[4][2];
#pragma unroll
            for (int np = 0; np < 2; np++) {
                const unsigned nro = (unsigned)((wn * 32 + np * 16) * 128);
                const unsigned off = nro + bRow + ((cb + bKq) ^ rx);
                ldm_x4(bh[np*2][0], bh[np*2][1], bh[np*2+1][0], bh[np*2+1][1], BsH + off);
                ldm_x4(bl[np*2][0], bl[np*2][1], bl[np*2+1][0], bl[np*2+1][1], BsL + off);
            }
            // ---- A fragments per m16-tile; 3 passes into same acc ----
#pragma unroll
            for (int mt = 0; mt < 4; mt++) {
                const unsigned mro = (unsigned)((wm * 64 + mt * 16) * 128);
                const unsigned off = mro + aRow + ((cb + aKq) ^ rx);
                unsigned ah[4], al[4];
                ldm_x4(ah[0], ah[1], ah[2], ah[3], AsH + off);
                ldm_x4(al[0], al[1], al[2], al[3], AsL + off);
#pragma unroll
                for (int nt = 0; nt < 4; nt++) {
                    mma16816(acc[mt][nt], ah, bh[nt]);
                    mma16816(acc[mt][nt], ah, bl[nt]);
                    mma16816(acc[mt][nt], al, bh[nt]);
                }
            }
        }
        __syncthreads();
    }

    // ---- epilogue: fragment layout -> g_G with bias ----
#pragma unroll
    for (int nt = 0; nt < 4; nt++) {
        const int col = col0 + wn * 32 + nt * 8 + (lane & 3) * 2;
        const float bv0 = bias[col], bv1 = bias[col + 1];
#pragma unroll
        for (int mt = 0; mt < 4; mt++) {
            const int row = row0 + wm * 64 + mt * 16 + (lane >> 2);
            float2 lo = { acc[mt][nt][0] + bv0, acc[mt][nt][1] + bv1 };
            float2 hi = { acc[mt][nt][2] + bv0, acc[mt][nt][3] + bv1 };
            *(float2*)(g_G + (size_t)row * G4H + col)       = lo;
            *(float2*)(g_G + (size_t)(row + 8) * G4H + col) = hi;
        }
    }
}

// ---------------- kernel 3: persistent LSTM recurrence (R13 + group bars) -
#define RCTAS    128
#define RTHREADS 512
#define US_F4    (256 * 32)
#define HS_F4    (256 * 2)
#define RED_F4   (16 * 8 * 32)
#define RSMEM    ((US_F4 + HS_F4 + RED_F4) * 16)          /* 204800 B */

__global__ void __launch_bounds__(RTHREADS, 1)
recur_kernel(const float* __restrict__ X,
             const float* __restrict__ U,
             float* __restrict__ out_enc) {
    extern __shared__ float4 smem4[];
    float4* Us4  = smem4;
    float4* hs4  = smem4 + US_F4;
    float4* red4 = smem4 + US_F4 + HS_F4;

    const int tid = threadIdx.x;
    const int cta = blockIdx.x;
    const int b0  = (cta & 15) * 8;
    const int j0  = (cta >> 4) * 32;
    const int jj  = tid & 31;
    const int ke  = tid >> 5;
    volatile unsigned* barp = &g_barg[(cta & 15) * 32];

    for (int idx = tid; idx < US_F4; idx += RTHREADS) {
        const int k  = idx >> 5;
        const int jc = j0 + (idx & 31);
        const float* Uk = U + (size_t)k * 1024;
        Us4[idx] = make_float4(Uk[jc], Uk[256 + jc], Uk[512 + jc], Uk[768 + jc]);
    }

    const int b2 = tid >> 5;
    const int j2 = j0 + jj;
    float c = 0.f;
    if (tid < 256) {
        const float x0 = X[(size_t)(b0 + b2) * (TM1 * NIN)];
        c = x0;
        g_h[0][(b0 + b2) * Hd + j2] = x0;
    }
    __threadfence();
    __syncthreads();
    if (tid == 0) atomicAdd((unsigned*)barp, 1u);

    for (int t = 0; t < TM1; t++) {
        if (tid == 0) {
            const unsigned target = (unsigned)(t + 1) * 8u;
            while (*barp < target) { }
            __threadfence();
        }
        __syncthreads();

        float G0, G1, G2, G3;
        if (tid < 256) {
            const float* grp = g_G + ((size_t)(b0 + b2) * TM1 + t) * G4H + j2;
            G0 = grp[0];   G1 = grp[256];
            G2 = grp[512]; G3 = grp[768];
        }

        if (tid < 256) {
            const int k = tid;
            const float* hsrc = g_h[t & 1] + b0 * Hd + k;
            float4 lo, hi;
            lo.x = hsrc[0 * Hd]; lo.y = hsrc[1 * Hd];
            lo.z = hsrc[2 * Hd]; lo.w = hsrc[3 * Hd];
            hi.x = hsrc[4 * Hd]; hi.y = hsrc[5 * Hd];
            hi.z = hsrc[6 * Hd]; hi.w = hsrc[7 * Hd];
            hs4[k * 2]     = lo;
            hs4[k * 2 + 1] = hi;
        }
        __syncthreads();

        float acc[8][4];
#pragma unroll
        for (int b = 0; b < 8; b++)
#pragma unroll
            for (int g = 0; g < 4; g++) acc[b][g] = 0.f;

        const float4* up = Us4 + (ke * 16) * 32 + jj;
        const float4* hp = hs4 + (ke * 16) * 2;
#pragma unroll 4
        for (int kl = 0; kl < 16; kl++) {
            const float4 u  = up[kl * 32];
            const float4 h0 = hp[kl * 2];
            const float4 h1 = hp[kl * 2 + 1];
            acc[0][0] = fmaf(h0.x, u.x, acc[0][0]); acc[0][1] = fmaf(h0.x, u.y, acc[0][1]);
            acc[0][2] = fmaf(h0.x, u.z, acc[0][2]); acc[0][3] = fmaf(h0.x, u.w, acc[0][3]);
            acc[1][0] = fmaf(h0.y, u.x, acc[1][0]); acc[1][1] = fmaf(h0.y, u.y, acc[1][1]);
            acc[1][2] = fmaf(h0.y, u.z, acc[1][2]); acc[1][3] = fmaf(h0.y, u.w, acc[1][3]);
            acc[2][0] = fmaf(h0.z, u.x, acc[2][0]); acc[2][1] = fmaf(h0.z, u.y, acc[2][1]);
            acc[2][2] = fmaf(h0.z, u.z, acc[2][2]); acc[2][3] = fmaf(h0.z, u.w, acc[2][3]);
            acc[3][0] = fmaf(h0.w, u.x, acc[3][0]); acc[3][1] = fmaf(h0.w, u.y, acc[3][1]);
            acc[3][2] = fmaf(h0.w, u.z, acc[3][2]); acc[3][3] = fmaf(h0.w, u.w, acc[3][3]);
            acc[4][0] = fmaf(h1.x, u.x, acc[4][0]); acc[4][1] = fmaf(h1.x, u.y, acc[4][1]);
            acc[4][2] = fmaf(h1.x, u.z, acc[4][2]); acc[4][3] = fmaf(h1.x, u.w, acc[4][3]);
            acc[5][0] = fmaf(h1.y, u.x, acc[5][0]); acc[5][1] = fmaf(h1.y, u.y, acc[5][1]);
            acc[5][2] = fmaf(h1.y, u.z, acc[5][2]); acc[5][3] = fmaf(h1.y, u.w, acc[5][3]);
            acc[6][0] = fmaf(h1.z, u.x, acc[6][0]); acc[6][1] = fmaf(h1.z, u.y, acc[6][1]);
            acc[6][2] = fmaf(h1.z, u.z, acc[6][2]); acc[6][3] = fmaf(h1.z, u.w, acc[6][3]);
            acc[7][0] = fmaf(h1.w, u.x, acc[7][0]); acc[7][1] = fmaf(h1.w, u.y, acc[7][1]);
            acc[7][2] = fmaf(h1.w, u.z, acc[7][2]); acc[7][3] = fmaf(h1.w, u.w, acc[7][3]);
        }

        {
            float4* rw = red4 + (ke * 8) * 32 + jj;
#pragma unroll
            for (int b = 0; b < 8; b++)
                rw[b * 32] = make_float4(acc[b][0], acc[b][1], acc[b][2], acc[b][3]);
        }
        __syncthreads();

        if (tid < 256) {
            const float4* rr = red4 + b2 * 32 + jj;
            float4 s0 = rr[0];
#pragma unroll
            for (int k16 = 1; k16 < 16; k16++) {
                const float4 p = rr[k16 * 8 * 32];
                s0.x += p.x; s0.y += p.y; s0.z += p.z; s0.w += p.w;
            }
            const float zi = s0.x + G0;
            const float zf = s0.y + G1;
            const float zg = s0.z + G2;
            const float zo = s0.w + G3;

            c = sigm_f(zf) * c + sigm_f(zi) * tanh_f(zg);
            const float hn = sigm_f(zo) * tanh_f(c);

            g_h[(t + 1) & 1][(b0 + b2) * Hd + j2] = hn;
            out_enc[((size_t)(b0 + b2) * TM1 + t) * Hd + j2] = hn;
            __threadfence();
        }
        __syncthreads();
        if (tid == 0) atomicAdd((unsigned*)barp, 1u);
    }
}

// ---------------- launch ----------------
extern "C" void kernel_launch(void* const* d_in, const int* in_sizes, int n_in,
                              void* d_out, int out_size) {
    const float* X      = (const float*)d_in[0];
    const float* W_attn = (const float*)d_in[1];
    /* b_attn = d_in[2] : cancels in softmax */
    const float* W_lstm = (const float*)d_in[3];
    const float* U_lstm = (const float*)d_in[4];
    const float* b_lstm = (const float*)d_in[5];

    float* out     = (float*)d_out;
    float* out_xt  = out;                             // X_tilde  (B,Tm1,N)
    float* out_enc = out + (size_t)Bsz * TM1 * NIN;   // X_encoded (B,Tm1,H)

    cudaFuncSetAttribute(gemm_tc_kernel,
                         cudaFuncAttributeMaxDynamicSharedMemorySize, GC_SMEM);
    cudaFuncSetAttribute(recur_kernel,
                         cudaFuncAttributeMaxDynamicSharedMemorySize, RSMEM);

    reset_kernel<<<1, 512>>>();
    alpha_kernel<<<Bsz, 512>>>(X, W_attn, out_xt);
    convW_kernel<<<G4H, 256>>>(W_lstm);
    convA_kernel<<<(BT * NIN) / (256 * 4), 256>>>(out_xt);
    gemm_tc_kernel<<<dim3(8, 255), 256, GC_SMEM>>>(b_lstm);
    recur_kernel<<<RCTAS, RTHREADS, RSMEM>>>(X, U_lstm, out_enc);
}